// round 12
// baseline (speedup 1.0000x reference)
#include <cuda_runtime.h>
#include <cstdint>

#define N_  128
#define C_  64
#define T_  288
#define V_  16
#define S_  3
#define IC_ 16

// tiny scratch: attention matrices after softmax + A  [N, S, V, V]
__device__ float g_att[N_ * S_ * V_ * V_];

// ---- packed f32x2 helpers ------------------------------------------------
__device__ __forceinline__ unsigned long long pk2(float lo, float hi) {
    unsigned long long r;
    asm("mov.b64 %0, {%1, %2};" : "=l"(r) : "f"(lo), "f"(hi));
    return r;
}
__device__ __forceinline__ void ffma2(unsigned long long& acc,
                                      unsigned long long a,
                                      unsigned long long b) {
    asm("fma.rn.f32x2 %0, %1, %2, %0;" : "+l"(acc) : "l"(a), "l"(b));
}
__device__ __forceinline__ float2 upk(unsigned long long p) {
    float2 f;
    asm("mov.b64 {%0, %1}, %2;" : "=f"(f.x), "=f"(f.y) : "l"(p));
    return f;
}
__device__ __forceinline__ uint32_t f2tf32(float f) {
    uint32_t r;
    asm("cvt.rna.tf32.f32 %0, %1;" : "=r"(r) : "f"(f));
    return r;
}
__device__ __forceinline__ void mma_tf32(float& d0, float& d1, float& d2, float& d3,
                                         uint32_t a0, uint32_t a1, uint32_t a2, uint32_t a3,
                                         uint32_t b0, uint32_t b1) {
    asm volatile("mma.sync.aligned.m16n8k8.row.col.f32.tf32.tf32.f32 "
                 "{%0,%1,%2,%3}, {%4,%5,%6,%7}, {%8,%9}, {%0,%1,%2,%3};"
                 : "+f"(d0), "+f"(d1), "+f"(d2), "+f"(d3)
                 : "r"(a0), "r"(a1), "r"(a2), "r"(a3), "r"(b0), "r"(b1));
}

// ---------------------------------------------------------------------------
// Kernel A (tensor, 8-t chunks, 3 blocks/SM): unchanged from R11 (~140us)
// ---------------------------------------------------------------------------
#define XCPA 136
#define WABP 72
__global__ __launch_bounds__(256, 3) void attn_kernel(
    const float* __restrict__ x, const float* __restrict__ A_base,
    const float* __restrict__ PA, const float* __restrict__ Wa,
    const float* __restrict__ ba, const float* __restrict__ Wb,
    const float* __restrict__ bb)
{
    extern __shared__ float sm[];
    float* sXc   = sm;                          // [64][136]
    float* sF    = sm + 64 * XCPA;              // [32][136]
    float* sWab  = sF + 32 * XCPA;              // [32][72]
    float* spart = sWab + 32 * WABP;            // [8][256]

    __shared__ float sbias[32];
    __shared__ float satt[256];
    __shared__ float colmax[16], colinv[16];

    const int tid  = threadIdx.x;
    const int wid  = tid >> 5;
    const int lane = tid & 31;
    const int n = blockIdx.x / S_;
    const int s = blockIdx.x % S_;

    const int r    = lane >> 2;
    const int kq   = lane & 3;
    const int ncol = lane >> 2;

    {
        int i = tid >> 3, c8 = (tid & 7) * 8;
        const float* src = (i < 16)
            ? (Wa + (size_t)(s * 16 + i) * 64 + c8)
            : (Wb + (size_t)(s * 16 + (i - 16)) * 64 + c8);
        *reinterpret_cast<float4*>(sWab + i * WABP + c8)     = *reinterpret_cast<const float4*>(src);
        *reinterpret_cast<float4*>(sWab + i * WABP + c8 + 4) = *reinterpret_cast<const float4*>(src + 4);
    }
    if (tid < 16)      sbias[tid] = ba[s * 16 + tid];
    else if (tid < 32) sbias[tid] = bb[s * 16 + (tid - 16)];

    const float* xn = x + (size_t)n * (C_ * T_ * V_);

    for (int idx = tid; idx < 2048; idx += 256) {
        int c = idx >> 5, q = idx & 31;
        *reinterpret_cast<float4*>(sXc + c * XCPA + q * 4) =
            *reinterpret_cast<const float4*>(xn + (size_t)c * (T_ * V_) + q * 4);
    }
    __syncthreads();

    const int mt = wid & 1;
    const int n0 = (wid >> 1) * 32;
    const float b_r  = sbias[mt * 16 + r];
    const float b_r8 = sbias[mt * 16 + r + 8];
    const int row0 = mt * 16 + r;

    float gacc[2][4];
    gacc[0][0] = 0.f; gacc[0][1] = 0.f; gacc[0][2] = 0.f; gacc[0][3] = 0.f;
    gacc[1][0] = 0.f; gacc[1][1] = 0.f; gacc[1][2] = 0.f; gacc[1][3] = 0.f;

    const uint32_t* uWab = reinterpret_cast<const uint32_t*>(sWab);
    const uint32_t* uXc  = reinterpret_cast<const uint32_t*>(sXc);
    const uint32_t* uF   = reinterpret_cast<const uint32_t*>(sF);

    const int i2 = 2 * wid;

    for (int ch = 0; ch < 36; ch++) {
        float acc[4][4];
        #pragma unroll
        for (int nt = 0; nt < 4; nt++) {
            acc[nt][0] = b_r; acc[nt][1] = b_r;
            acc[nt][2] = b_r8; acc[nt][3] = b_r8;
        }
        #pragma unroll
        for (int ks = 0; ks < 8; ks++) {
            const int k0 = ks * 8;
            uint32_t a0 = uWab[row0 * WABP + k0 + kq];
            uint32_t a1 = uWab[(row0 + 8) * WABP + k0 + kq];
            uint32_t a2 = uWab[row0 * WABP + k0 + 4 + kq];
            uint32_t a3 = uWab[(row0 + 8) * WABP + k0 + 4 + kq];
            const uint32_t* bp0 = uXc + (k0 + kq) * XCPA + n0 + ncol;
            const uint32_t* bp1 = uXc + (k0 + 4 + kq) * XCPA + n0 + ncol;
            #pragma unroll
            for (int nt = 0; nt < 4; nt++) {
                mma_tf32(acc[nt][0], acc[nt][1], acc[nt][2], acc[nt][3],
                         a0, a1, a2, a3, bp0[nt * 8], bp1[nt * 8]);
            }
        }
        #pragma unroll
        for (int nt = 0; nt < 4; nt++) {
            const int col = n0 + nt * 8 + 2 * kq;
            *reinterpret_cast<float2*>(sF + row0 * XCPA + col) =
                make_float2(acc[nt][0], acc[nt][1]);
            *reinterpret_cast<float2*>(sF + (row0 + 8) * XCPA + col) =
                make_float2(acc[nt][2], acc[nt][3]);
        }
        __syncthreads();

        if (ch < 35) {
            const float* src = xn + (ch + 1) * 128;
            for (int idx = tid; idx < 2048; idx += 256) {
                int c = idx >> 5, q = idx & 31;
                *reinterpret_cast<float4*>(sXc + c * XCPA + q * 4) =
                    *reinterpret_cast<const float4*>(src + (size_t)c * (T_ * V_) + q * 4);
            }
        }

        #pragma unroll
        for (int ks = 0; ks < 2; ks++) {
            const int i = i2 + ks;
            uint32_t a0 = uF[i * XCPA + kq * 16 + r];
            uint32_t a1 = uF[i * XCPA + kq * 16 + r + 8];
            uint32_t a2 = uF[i * XCPA + (kq + 4) * 16 + r];
            uint32_t a3 = uF[i * XCPA + (kq + 4) * 16 + r + 8];
            #pragma unroll
            for (int nt = 0; nt < 2; nt++) {
                uint32_t b0 = uF[(16 + i) * XCPA + kq * 16 + nt * 8 + ncol];
                uint32_t b1 = uF[(16 + i) * XCPA + (kq + 4) * 16 + nt * 8 + ncol];
                mma_tf32(gacc[nt][0], gacc[nt][1], gacc[nt][2], gacc[nt][3],
                         a0, a1, a2, a3, b0, b1);
            }
        }
        __syncthreads();
    }

    #pragma unroll
    for (int nt = 0; nt < 2; nt++) {
        float* p = spart + wid * 256 + nt * 8 + 2 * kq;
        p[r * 16]           = gacc[nt][0];
        p[r * 16 + 1]       = gacc[nt][1];
        p[(r + 8) * 16]     = gacc[nt][2];
        p[(r + 8) * 16 + 1] = gacc[nt][3];
    }
    __syncthreads();

    float attacc = 0.f;
    #pragma unroll
    for (int w8 = 0; w8 < 8; w8++) attacc += spart[w8 * 256 + tid];
    attacc *= (1.0f / (float)(IC_ * T_));
    satt[tid] = attacc;
    __syncthreads();

    const int v = tid >> 4;
    const int w = tid & 15;
    if (tid < 16) {
        float m = -1e30f;
        #pragma unroll
        for (int vv = 0; vv < 16; vv++) m = fmaxf(m, satt[vv * 16 + tid]);
        float ssum = 0.f;
        #pragma unroll
        for (int vv = 0; vv < 16; vv++) ssum += __expf(satt[vv * 16 + tid] - m);
        colmax[tid] = m;
        colinv[tid] = 1.0f / ssum;
    }
    __syncthreads();

    float rr = __expf(attacc - colmax[w]) * colinv[w]
             + A_base[(s * 16 + v) * 16 + w] + PA[(s * 16 + v) * 16 + w];
    g_att[((n * 3 + s) * 16 + v) * 16 + w] = rr;
}

// ---------------------------------------------------------------------------
// Kernel B (R8 structure, SINGLE W buffer -> 93184 B smem -> 2 blocks/SM):
//   W_{s+1} prefetched to regs during stage1, stored to smem after stage2's
//   sync (visibility covered by next iteration's post-stage1 sync).
// smem: sZ 37888 @0 (sO reuse) | sW 18432 @37888 | sX 33792 @56320 | att @90112
// ---------------------------------------------------------------------------
#define ZP 74
#define WP 72
#define XP 132
__global__ __launch_bounds__(256, 2) void out_kernel(
    const float* __restrict__ x, const float* __restrict__ Wd,
    const float* __restrict__ bd, const float* __restrict__ gamma,
    const float* __restrict__ beta, float* __restrict__ out)
{
    extern __shared__ char smem[];
    uint32_t* sZ  = (uint32_t*)(smem);                 // [128][ZP] tf32
    float*    sO  = (float*)(smem);                    // epilogue reuse [64][XP]
    uint32_t* sW  = (uint32_t*)(smem + 37888);         // [64][WP] tf32 (single)
    float*    sX  = (float*)(smem + 56320);            // [64][XP]
    float*    sAtt= (float*)(smem + 90112);            // [3][16][16]

    __shared__ float sBN[3 * 64];

    const int tid  = threadIdx.x;
    const int wid  = tid >> 5;
    const int lane = tid & 31;
    const int n  = blockIdx.y;
    const int t0 = blockIdx.x * 8;

    for (int idx = tid; idx < 768; idx += 256)
        sAtt[idx] = g_att[n * 768 + idx];
    for (int idx = tid; idx < 64 * 32; idx += 256) {
        int c = idx >> 5, q = idx & 31;
        reinterpret_cast<float4*>(sX + c * XP)[q] =
            reinterpret_cast<const float4*>(x + (size_t)(n * 64 + c) * (T_ * V_) + t0 * V_)[q];
    }
    #pragma unroll
    for (int q = 0; q < 4; q++) {
        int i4 = tid * 4 + q;              // o = i4>>4, c-quad = i4&15
        int o = i4 >> 4, c4 = i4 & 15;
        float4 wv = reinterpret_cast<const float4*>(Wd)[i4];
        sW[(c4 * 4 + 0) * WP + o] = f2tf32(wv.x);
        sW[(c4 * 4 + 1) * WP + o] = f2tf32(wv.y);
        sW[(c4 * 4 + 2) * WP + o] = f2tf32(wv.z);
        sW[(c4 * 4 + 3) * WP + o] = f2tf32(wv.w);
    }
    if (tid < 64) {
        int o = tid;
        sBN[o]       = bd[o] + bd[64 + o] + bd[128 + o];
        sBN[64 + o]  = gamma[o] * rsqrtf(1.0f + 1e-5f);
        sBN[128 + o] = beta[o];
    }
    __syncthreads();

    const int c1 = tid >> 2;
    const int wg = tid & 3;

    const int m0   = wid * 16;
    const int rA0  = m0 + (lane >> 2);
    const int kq   = lane & 3;
    const int ncol = lane >> 2;

    float acc[8][4];
    #pragma unroll
    for (int nf = 0; nf < 8; nf++) {
        acc[nf][0] = 0.f; acc[nf][1] = 0.f; acc[nf][2] = 0.f; acc[nf][3] = 0.f;
    }

    #pragma unroll
    for (int s = 0; s < S_; s++) {
        // ---- stage1: Z_s[tw][c1] tf32 (conflict-free with ZP=74)
        ulonglong2 ar[16];
        #pragma unroll
        for (int v = 0; v < 16; v++)
            ar[v] = *reinterpret_cast<const ulonglong2*>(sAtt + s * 256 + v * 16 + wg * 4);

        #pragma unroll
        for (int tt = 0; tt < 8; tt++) {
            const float4* xp = reinterpret_cast<const float4*>(sX + c1 * XP + tt * 16);
            float xr[16];
            #pragma unroll
            for (int q = 0; q < 4; q++) {
                float4 xx = xp[q];
                xr[q * 4 + 0] = xx.x; xr[q * 4 + 1] = xx.y;
                xr[q * 4 + 2] = xx.z; xr[q * 4 + 3] = xx.w;
            }
            unsigned long long a0 = 0ull, a1 = 0ull;
            #pragma unroll
            for (int v = 0; v < 16; v++) {
                unsigned long long xd = pk2(xr[v], xr[v]);
                ffma2(a0, xd, ar[v].x);
                ffma2(a1, xd, ar[v].y);
            }
            float2 f0 = upk(a0), f1 = upk(a1);
            const int twb = tt * 16 + wg * 4;
            sZ[(twb + 0) * ZP + c1] = f2tf32(f0.x);
            sZ[(twb + 1) * ZP + c1] = f2tf32(f0.y);
            sZ[(twb + 2) * ZP + c1] = f2tf32(f1.x);
            sZ[(twb + 3) * ZP + c1] = f2tf32(f1.y);
        }

        // prefetch W_{s+1} into registers (latency hidden behind stage1/stage2)
        float4 wv[4];
        if (s < 2) {
            const float4* src = reinterpret_cast<const float4*>(Wd + (size_t)(s + 1) * 4096);
            #pragma unroll
            for (int q = 0; q < 4; q++) wv[q] = src[tid * 4 + q];
        }
        __syncthreads();   // Z_s visible; sW holds W_s (stored last iteration)

        // ---- stage2: 8 k-steps of m16n8k8 over c
        #pragma unroll
        for (int ks = 0; ks < 8; ks++) {
            const int k0 = ks * 8;
            uint32_t a0 = sZ[rA0 * ZP + k0 + kq];
            uint32_t a1 = sZ[(rA0 + 8) * ZP + k0 + kq];
            uint32_t a2 = sZ[rA0 * ZP + k0 + 4 + kq];
            uint32_t a3 = sZ[(rA0 + 8) * ZP + k0 + 4 + kq];
            const uint32_t* bp0 = sW + (k0 + kq) * WP + ncol;
            const uint32_t* bp1 = sW + (k0 + 4 + kq) * WP + ncol;
            #pragma unroll
            for (int nf = 0; nf < 8; nf++) {
                uint32_t b0 = bp0[nf * 8];
                uint32_t b1 = bp1[nf * 8];
                mma_tf32(acc[nf][0], acc[nf][1], acc[nf][2], acc[nf][3],
                         a0, a1, a2, a3, b0, b1);
            }
        }
        __syncthreads();   // stage2 reads of sZ + sW done

        // store W_{s+1} (visibility guaranteed by next iteration's sync)
        if (s < 2) {
            #pragma unroll
            for (int q = 0; q < 4; q++) {
                int i4 = tid * 4 + q;
                int o = i4 >> 4, c4 = i4 & 15;
                sW[(c4 * 4 + 0) * WP + o] = f2tf32(wv[q].x);
                sW[(c4 * 4 + 1) * WP + o] = f2tf32(wv[q].y);
                sW[(c4 * 4 + 2) * WP + o] = f2tf32(wv[q].z);
                sW[(c4 * 4 + 3) * WP + o] = f2tf32(wv[q].w);
            }
        }
    }

    // ---- epilogue: BN+bias into sO[o][tw] (pitch 132, conflict-free)
    {
        const int r0 = m0 + (lane >> 2);
        #pragma unroll
        for (int nf = 0; nf < 8; nf++) {
            int o0 = nf * 8 + 2 * (lane & 3);
            float s0 = sBN[64 + o0],     b0v = sBN[o0],     z0 = sBN[128 + o0];
            float s1 = sBN[64 + o0 + 1], b1v = sBN[o0 + 1], z1 = sBN[128 + o0 + 1];
            sO[o0 * XP + r0]           = (acc[nf][0] + b0v) * s0 + z0;
            sO[(o0 + 1) * XP + r0]     = (acc[nf][1] + b1v) * s1 + z1;
            sO[o0 * XP + r0 + 8]       = (acc[nf][2] + b0v) * s0 + z0;
            sO[(o0 + 1) * XP + r0 + 8] = (acc[nf][3] + b1v) * s1 + z1;
        }
    }
    __syncthreads();

    for (int idx = tid; idx < 64 * 32; idx += 256) {
        int c = idx >> 5, q = idx & 31;
        float4 yv = reinterpret_cast<const float4*>(sO + c * XP)[q];
        float4 xv = reinterpret_cast<const float4*>(sX + c * XP)[q];
        yv.x += xv.x; yv.y += xv.y; yv.z += xv.z; yv.w += xv.w;
        reinterpret_cast<float4*>(out + (size_t)(n * 64 + c) * (T_ * V_) + t0 * V_)[q] = yv;
    }
}

extern "C" void kernel_launch(void* const* d_in, const int* in_sizes, int n_in,
                              void* d_out, int out_size)
{
    const float* x      = (const float*)d_in[0];
    const float* A_base = (const float*)d_in[1];
    const float* PA     = (const float*)d_in[2];
    const float* Wa     = (const float*)d_in[3];
    const float* ba     = (const float*)d_in[4];
    const float* Wb     = (const float*)d_in[5];
    const float* bb     = (const float*)d_in[6];
    const float* Wd     = (const float*)d_in[7];
    const float* bd     = (const float*)d_in[8];
    const float* gamma  = (const float*)d_in[9];
    const float* beta   = (const float*)d_in[10];
    float* out = (float*)d_out;

    const int smemA = (64 * XCPA + 32 * XCPA + 32 * WABP + 8 * 256) * sizeof(float); // 69632 B
    const int smemB = 93184;                                                         // bytes

    cudaFuncSetAttribute(attn_kernel, cudaFuncAttributeMaxDynamicSharedMemorySize, smemA);
    cudaFuncSetAttribute(out_kernel,  cudaFuncAttributeMaxDynamicSharedMemorySize, smemB);

    attn_kernel<<<N_ * S_, 256, smemA>>>(x, A_base, PA, Wa, ba, Wb, bb);
    out_kernel<<<dim3(T_ / 8, N_), 256, smemB>>>(x, Wd, bd, gamma, beta, out);
}

// round 13
// speedup vs baseline: 1.0815x; 1.0815x over previous
#include <cuda_runtime.h>
#include <cstdint>

#define N_  128
#define C_  64
#define T_  288
#define V_  16
#define S_  3
#define IC_ 16

// tiny scratch: attention matrices after softmax + A  [N, S, V, V]
__device__ float g_att[N_ * S_ * V_ * V_];

// ---- packed f32x2 helpers ------------------------------------------------
__device__ __forceinline__ unsigned long long pk2(float lo, float hi) {
    unsigned long long r;
    asm("mov.b64 %0, {%1, %2};" : "=l"(r) : "f"(lo), "f"(hi));
    return r;
}
__device__ __forceinline__ void ffma2(unsigned long long& acc,
                                      unsigned long long a,
                                      unsigned long long b) {
    asm("fma.rn.f32x2 %0, %1, %2, %0;" : "+l"(acc) : "l"(a), "l"(b));
}
__device__ __forceinline__ float2 upk(unsigned long long p) {
    float2 f;
    asm("mov.b64 {%0, %1}, %2;" : "=f"(f.x), "=f"(f.y) : "l"(p));
    return f;
}
__device__ __forceinline__ uint32_t f2tf32(float f) {
    uint32_t r;
    asm("cvt.rna.tf32.f32 %0, %1;" : "=r"(r) : "f"(f));
    return r;
}
__device__ __forceinline__ void mma_tf32(float& d0, float& d1, float& d2, float& d3,
                                         uint32_t a0, uint32_t a1, uint32_t a2, uint32_t a3,
                                         uint32_t b0, uint32_t b1) {
    asm volatile("mma.sync.aligned.m16n8k8.row.col.f32.tf32.tf32.f32 "
                 "{%0,%1,%2,%3}, {%4,%5,%6,%7}, {%8,%9}, {%0,%1,%2,%3};"
                 : "+f"(d0), "+f"(d1), "+f"(d2), "+f"(d3)
                 : "r"(a0), "r"(a1), "r"(a2), "r"(a3), "r"(b0), "r"(b1));
}

// ---------------------------------------------------------------------------
// Kernel A (tensor, 8-t chunks, 3 blocks/SM): unchanged from R11 (~140us)
// ---------------------------------------------------------------------------
#define XCPA 136
#define WABP 72
__global__ __launch_bounds__(256, 3) void attn_kernel(
    const float* __restrict__ x, const float* __restrict__ A_base,
    const float* __restrict__ PA, const float* __restrict__ Wa,
    const float* __restrict__ ba, const float* __restrict__ Wb,
    const float* __restrict__ bb)
{
    extern __shared__ float sm[];
    float* sXc   = sm;                          // [64][136]
    float* sF    = sm + 64 * XCPA;              // [32][136]
    float* sWab  = sF + 32 * XCPA;              // [32][72]
    float* spart = sWab + 32 * WABP;            // [8][256]

    __shared__ float sbias[32];
    __shared__ float satt[256];
    __shared__ float colmax[16], colinv[16];

    const int tid  = threadIdx.x;
    const int wid  = tid >> 5;
    const int lane = tid & 31;
    const int n = blockIdx.x / S_;
    const int s = blockIdx.x % S_;

    const int r    = lane >> 2;
    const int kq   = lane & 3;
    const int ncol = lane >> 2;

    {
        int i = tid >> 3, c8 = (tid & 7) * 8;
        const float* src = (i < 16)
            ? (Wa + (size_t)(s * 16 + i) * 64 + c8)
            : (Wb + (size_t)(s * 16 + (i - 16)) * 64 + c8);
        *reinterpret_cast<float4*>(sWab + i * WABP + c8)     = *reinterpret_cast<const float4*>(src);
        *reinterpret_cast<float4*>(sWab + i * WABP + c8 + 4) = *reinterpret_cast<const float4*>(src + 4);
    }
    if (tid < 16)      sbias[tid] = ba[s * 16 + tid];
    else if (tid < 32) sbias[tid] = bb[s * 16 + (tid - 16)];

    const float* xn = x + (size_t)n * (C_ * T_ * V_);

    for (int idx = tid; idx < 2048; idx += 256) {
        int c = idx >> 5, q = idx & 31;
        *reinterpret_cast<float4*>(sXc + c * XCPA + q * 4) =
            *reinterpret_cast<const float4*>(xn + (size_t)c * (T_ * V_) + q * 4);
    }
    __syncthreads();

    const int mt = wid & 1;
    const int n0 = (wid >> 1) * 32;
    const float b_r  = sbias[mt * 16 + r];
    const float b_r8 = sbias[mt * 16 + r + 8];
    const int row0 = mt * 16 + r;

    float gacc[2][4];
    gacc[0][0] = 0.f; gacc[0][1] = 0.f; gacc[0][2] = 0.f; gacc[0][3] = 0.f;
    gacc[1][0] = 0.f; gacc[1][1] = 0.f; gacc[1][2] = 0.f; gacc[1][3] = 0.f;

    const uint32_t* uWab = reinterpret_cast<const uint32_t*>(sWab);
    const uint32_t* uXc  = reinterpret_cast<const uint32_t*>(sXc);
    const uint32_t* uF   = reinterpret_cast<const uint32_t*>(sF);

    const int i2 = 2 * wid;

    for (int ch = 0; ch < 36; ch++) {
        float acc[4][4];
        #pragma unroll
        for (int nt = 0; nt < 4; nt++) {
            acc[nt][0] = b_r; acc[nt][1] = b_r;
            acc[nt][2] = b_r8; acc[nt][3] = b_r8;
        }
        #pragma unroll
        for (int ks = 0; ks < 8; ks++) {
            const int k0 = ks * 8;
            uint32_t a0 = uWab[row0 * WABP + k0 + kq];
            uint32_t a1 = uWab[(row0 + 8) * WABP + k0 + kq];
            uint32_t a2 = uWab[row0 * WABP + k0 + 4 + kq];
            uint32_t a3 = uWab[(row0 + 8) * WABP + k0 + 4 + kq];
            const uint32_t* bp0 = uXc + (k0 + kq) * XCPA + n0 + ncol;
            const uint32_t* bp1 = uXc + (k0 + 4 + kq) * XCPA + n0 + ncol;
            #pragma unroll
            for (int nt = 0; nt < 4; nt++) {
                mma_tf32(acc[nt][0], acc[nt][1], acc[nt][2], acc[nt][3],
                         a0, a1, a2, a3, bp0[nt * 8], bp1[nt * 8]);
            }
        }
        #pragma unroll
        for (int nt = 0; nt < 4; nt++) {
            const int col = n0 + nt * 8 + 2 * kq;
            *reinterpret_cast<float2*>(sF + row0 * XCPA + col) =
                make_float2(acc[nt][0], acc[nt][1]);
            *reinterpret_cast<float2*>(sF + (row0 + 8) * XCPA + col) =
                make_float2(acc[nt][2], acc[nt][3]);
        }
        __syncthreads();

        if (ch < 35) {
            const float* src = xn + (ch + 1) * 128;
            for (int idx = tid; idx < 2048; idx += 256) {
                int c = idx >> 5, q = idx & 31;
                *reinterpret_cast<float4*>(sXc + c * XCPA + q * 4) =
                    *reinterpret_cast<const float4*>(src + (size_t)c * (T_ * V_) + q * 4);
            }
        }

        #pragma unroll
        for (int ks = 0; ks < 2; ks++) {
            const int i = i2 + ks;
            uint32_t a0 = uF[i * XCPA + kq * 16 + r];
            uint32_t a1 = uF[i * XCPA + kq * 16 + r + 8];
            uint32_t a2 = uF[i * XCPA + (kq + 4) * 16 + r];
            uint32_t a3 = uF[i * XCPA + (kq + 4) * 16 + r + 8];
            #pragma unroll
            for (int nt = 0; nt < 2; nt++) {
                uint32_t b0 = uF[(16 + i) * XCPA + kq * 16 + nt * 8 + ncol];
                uint32_t b1 = uF[(16 + i) * XCPA + (kq + 4) * 16 + nt * 8 + ncol];
                mma_tf32(gacc[nt][0], gacc[nt][1], gacc[nt][2], gacc[nt][3],
                         a0, a1, a2, a3, b0, b1);
            }
        }
        __syncthreads();
    }

    #pragma unroll
    for (int nt = 0; nt < 2; nt++) {
        float* p = spart + wid * 256 + nt * 8 + 2 * kq;
        p[r * 16]           = gacc[nt][0];
        p[r * 16 + 1]       = gacc[nt][1];
        p[(r + 8) * 16]     = gacc[nt][2];
        p[(r + 8) * 16 + 1] = gacc[nt][3];
    }
    __syncthreads();

    float attacc = 0.f;
    #pragma unroll
    for (int w8 = 0; w8 < 8; w8++) attacc += spart[w8 * 256 + tid];
    attacc *= (1.0f / (float)(IC_ * T_));
    satt[tid] = attacc;
    __syncthreads();

    const int v = tid >> 4;
    const int w = tid & 15;
    if (tid < 16) {
        float m = -1e30f;
        #pragma unroll
        for (int vv = 0; vv < 16; vv++) m = fmaxf(m, satt[vv * 16 + tid]);
        float ssum = 0.f;
        #pragma unroll
        for (int vv = 0; vv < 16; vv++) ssum += __expf(satt[vv * 16 + tid] - m);
        colmax[tid] = m;
        colinv[tid] = 1.0f / ssum;
    }
    __syncthreads();

    float rr = __expf(attacc - colmax[w]) * colinv[w]
             + A_base[(s * 16 + v) * 16 + w] + PA[(s * 16 + v) * 16 + w];
    g_att[((n * 3 + s) * 16 + v) * 16 + w] = rr;
}

// ---------------------------------------------------------------------------
// Kernel B v2: BOTH stages on tensor pipe.
//   stage1 (mma, warp-private): warp wid owns t=t0+wid.
//     Z_t[16w][64c] = att_s^T[16w,16v] @ X_t[16v,64c]  (2 k-steps x 8 n-tiles)
//     B-frags read from sX (pitch 132, conflict-free); D stored to warp's own
//     sZ rows (rna->tf32), only __syncwarp needed.
//   stage2 (mma): unchanged from R12 (A from own sZ rows, B from sW).
//   Block barriers: 2 per s (single W buffer), as in R12.
// smem: sZ 37888 @0 (sO reuse) | sW 18432 @37888 | sX 33792 @56320 | att @90112
// ---------------------------------------------------------------------------
#define ZP 74
#define WP 72
#define XP 132
__global__ __launch_bounds__(256, 2) void out_kernel(
    const float* __restrict__ x, const float* __restrict__ Wd,
    const float* __restrict__ bd, const float* __restrict__ gamma,
    const float* __restrict__ beta, float* __restrict__ out)
{
    extern __shared__ char smem[];
    uint32_t* sZ  = (uint32_t*)(smem);                 // [128][ZP] tf32
    float*    sO  = (float*)(smem);                    // epilogue reuse [64][XP]
    uint32_t* sW  = (uint32_t*)(smem + 37888);         // [64][WP] tf32 (single)
    float*    sX  = (float*)(smem + 56320);            // [64][XP]
    float*    sAtt= (float*)(smem + 90112);            // [3][16][16]

    __shared__ float sBN[3 * 64];

    const int tid  = threadIdx.x;
    const int wid  = tid >> 5;
    const int lane = tid & 31;
    const int n  = blockIdx.y;
    const int t0 = blockIdx.x * 8;

    for (int idx = tid; idx < 768; idx += 256)
        sAtt[idx] = g_att[n * 768 + idx];
    for (int idx = tid; idx < 64 * 32; idx += 256) {
        int c = idx >> 5, q = idx & 31;
        reinterpret_cast<float4*>(sX + c * XP)[q] =
            reinterpret_cast<const float4*>(x + (size_t)(n * 64 + c) * (T_ * V_) + t0 * V_)[q];
    }
    #pragma unroll
    for (int q = 0; q < 4; q++) {
        int i4 = tid * 4 + q;              // o = i4>>4, c-quad = i4&15
        int o = i4 >> 4, c4 = i4 & 15;
        float4 wv = reinterpret_cast<const float4*>(Wd)[i4];
        sW[(c4 * 4 + 0) * WP + o] = f2tf32(wv.x);
        sW[(c4 * 4 + 1) * WP + o] = f2tf32(wv.y);
        sW[(c4 * 4 + 2) * WP + o] = f2tf32(wv.z);
        sW[(c4 * 4 + 3) * WP + o] = f2tf32(wv.w);
    }
    if (tid < 64) {
        int o = tid;
        sBN[o]       = bd[o] + bd[64 + o] + bd[128 + o];
        sBN[64 + o]  = gamma[o] * rsqrtf(1.0f + 1e-5f);
        sBN[128 + o] = beta[o];
    }
    __syncthreads();

    const int m0   = wid * 16;
    const int r    = lane >> 2;
    const int kq   = lane & 3;
    const int ncol = lane >> 2;
    const int rA0  = m0 + r;

    const uint32_t* uX = reinterpret_cast<const uint32_t*>(sX);
    const uint32_t* uA = reinterpret_cast<const uint32_t*>(sAtt);

    float acc[8][4];
    #pragma unroll
    for (int nf = 0; nf < 8; nf++) {
        acc[nf][0] = 0.f; acc[nf][1] = 0.f; acc[nf][2] = 0.f; acc[nf][3] = 0.f;
    }

    #pragma unroll
    for (int s = 0; s < S_; s++) {
        // ---- stage1 (tensor): D = att_s^T @ X_t, warp-private
        float d[8][4];
        #pragma unroll
        for (int nf = 0; nf < 8; nf++) {
            d[nf][0] = 0.f; d[nf][1] = 0.f; d[nf][2] = 0.f; d[nf][3] = 0.f;
        }
        #pragma unroll
        for (int ks = 0; ks < 2; ks++) {
            // A-frag: A[m=w][k=v] = att[s][v][w]
            const int v0 = ks * 8 + kq;
            uint32_t a0 = uA[s * 256 + v0 * 16 + r];
            uint32_t a1 = uA[s * 256 + v0 * 16 + r + 8];
            uint32_t a2 = uA[s * 256 + (v0 + 4) * 16 + r];
            uint32_t a3 = uA[s * 256 + (v0 + 4) * 16 + r + 8];
            const uint32_t* bx = uX + wid * 16 + ks * 8 + kq;
            #pragma unroll
            for (int nf = 0; nf < 8; nf++) {
                uint32_t b0 = bx[(nf * 8 + ncol) * XP];
                uint32_t b1 = bx[(nf * 8 + ncol) * XP + 4];
                mma_tf32(d[nf][0], d[nf][1], d[nf][2], d[nf][3],
                         a0, a1, a2, a3, b0, b1);
            }
        }
        // store D (tf32) to this warp's own sZ rows
        #pragma unroll
        for (int nf = 0; nf < 8; nf++) {
            uint32_t* p0 = sZ + (rA0)     * ZP + nf * 8 + 2 * kq;
            uint32_t* p1 = sZ + (rA0 + 8) * ZP + nf * 8 + 2 * kq;
            p0[0] = f2tf32(d[nf][0]); p0[1] = f2tf32(d[nf][1]);
            p1[0] = f2tf32(d[nf][2]); p1[1] = f2tf32(d[nf][3]);
        }
        __syncwarp();

        // prefetch W_{s+1} into registers
        float4 wv[4];
        if (s < 2) {
            const float4* src = reinterpret_cast<const float4*>(Wd + (size_t)(s + 1) * 4096);
            #pragma unroll
            for (int q = 0; q < 4; q++) wv[q] = src[tid * 4 + q];
        }
        __syncthreads();   // W_s (stored last iteration) visible

        // ---- stage2: 8 k-steps of m16n8k8 over c (A = own sZ rows, B = sW)
        #pragma unroll
        for (int ks = 0; ks < 8; ks++) {
            const int k0 = ks * 8;
            uint32_t a0 = sZ[rA0 * ZP + k0 + kq];
            uint32_t a1 = sZ[(rA0 + 8) * ZP + k0 + kq];
            uint32_t a2 = sZ[rA0 * ZP + k0 + 4 + kq];
            uint32_t a3 = sZ[(rA0 + 8) * ZP + k0 + 4 + kq];
            const uint32_t* bp0 = sW + (k0 + kq) * WP + ncol;
            const uint32_t* bp1 = sW + (k0 + 4 + kq) * WP + ncol;
            #pragma unroll
            for (int nf = 0; nf < 8; nf++) {
                uint32_t b0 = bp0[nf * 8];
                uint32_t b1 = bp1[nf * 8];
                mma_tf32(acc[nf][0], acc[nf][1], acc[nf][2], acc[nf][3],
                         a0, a1, a2, a3, b0, b1);
            }
        }
        __syncthreads();   // stage2 reads of sW done

        // store W_{s+1} (visibility via next iteration's barrier)
        if (s < 2) {
            #pragma unroll
            for (int q = 0; q < 4; q++) {
                int i4 = tid * 4 + q;
                int o = i4 >> 4, c4 = i4 & 15;
                sW[(c4 * 4 + 0) * WP + o] = f2tf32(wv[q].x);
                sW[(c4 * 4 + 1) * WP + o] = f2tf32(wv[q].y);
                sW[(c4 * 4 + 2) * WP + o] = f2tf32(wv[q].z);
                sW[(c4 * 4 + 3) * WP + o] = f2tf32(wv[q].w);
            }
        }
    }

    // ---- epilogue: BN+bias into sO[o][tw] (pitch 132), coalesced store
    {
        const int r0 = m0 + r;
        #pragma unroll
        for (int nf = 0; nf < 8; nf++) {
            int o0 = nf * 8 + 2 * kq;
            float s0 = sBN[64 + o0],     b0v = sBN[o0],     z0 = sBN[128 + o0];
            float s1 = sBN[64 + o0 + 1], b1v = sBN[o0 + 1], z1 = sBN[128 + o0 + 1];
            sO[o0 * XP + r0]           = (acc[nf][0] + b0v) * s0 + z0;
            sO[(o0 + 1) * XP + r0]     = (acc[nf][1] + b1v) * s1 + z1;
            sO[o0 * XP + r0 + 8]       = (acc[nf][2] + b0v) * s0 + z0;
            sO[(o0 + 1) * XP + r0 + 8] = (acc[nf][3] + b1v) * s1 + z1;
        }
    }
    __syncthreads();

    for (int idx = tid; idx < 64 * 32; idx += 256) {
        int c = idx >> 5, q = idx & 31;
        float4 yv = reinterpret_cast<const float4*>(sO + c * XP)[q];
        float4 xv = reinterpret_cast<const float4*>(sX + c * XP)[q];
        yv.x += xv.x; yv.y += xv.y; yv.z += xv.z; yv.w += xv.w;
        reinterpret_cast<float4*>(out + (size_t)(n * 64 + c) * (T_ * V_) + t0 * V_)[q] = yv;
    }
}

extern "C" void kernel_launch(void* const* d_in, const int* in_sizes, int n_in,
                              void* d_out, int out_size)
{
    const float* x      = (const float*)d_in[0];
    const float* A_base = (const float*)d_in[1];
    const float* PA     = (const float*)d_in[2];
    const float* Wa     = (const float*)d_in[3];
    const float* ba     = (const float*)d_in[4];
    const float* Wb     = (const float*)d_in[5];
    const float* bb     = (const float*)d_in[6];
    const float* Wd     = (const float*)d_in[7];
    const float* bd     = (const float*)d_in[8];
    const float* gamma  = (const float*)d_in[9];
    const float* beta   = (const float*)d_in[10];
    float* out = (float*)d_out;

    const int smemA = (64 * XCPA + 32 * XCPA + 32 * WABP + 8 * 256) * sizeof(float); // 69632 B
    const int smemB = 93184;                                                         // bytes

    cudaFuncSetAttribute(attn_kernel, cudaFuncAttributeMaxDynamicSharedMemorySize, smemA);
    cudaFuncSetAttribute(out_kernel,  cudaFuncAttributeMaxDynamicSharedMemorySize, smemB);

    attn_kernel<<<N_ * S_, 256, smemA>>>(x, A_base, PA, Wa, ba, Wb, bb);
    out_kernel<<<dim3(T_ / 8, N_), 256, smemB>>>(x, Wd, bd, gamma, beta, out);
}

// round 14
// speedup vs baseline: 1.0915x; 1.0092x over previous
#include <cuda_runtime.h>
#include <cstdint>

#define N_  128
#define C_  64
#define T_  288
#define V_  16
#define S_  3
#define IC_ 16

// tiny scratch: attention matrices after softmax + A  [N, S, V, V]
__device__ float g_att[N_ * S_ * V_ * V_];

// ---- helpers ------------------------------------------------------------
__device__ __forceinline__ uint32_t f2tf32(float f) {
    uint32_t r;
    asm("cvt.rna.tf32.f32 %0, %1;" : "=r"(r) : "f"(f));
    return r;
}
__device__ __forceinline__ void mma_tf32(float& d0, float& d1, float& d2, float& d3,
                                         uint32_t a0, uint32_t a1, uint32_t a2, uint32_t a3,
                                         uint32_t b0, uint32_t b1) {
    asm volatile("mma.sync.aligned.m16n8k8.row.col.f32.tf32.tf32.f32 "
                 "{%0,%1,%2,%3}, {%4,%5,%6,%7}, {%8,%9}, {%0,%1,%2,%3};"
                 : "+f"(d0), "+f"(d1), "+f"(d2), "+f"(d3)
                 : "r"(a0), "r"(a1), "r"(a2), "r"(a3), "r"(b0), "r"(b1));
}

// ---------------------------------------------------------------------------
// Kernel A (tensor, 8-t chunks, 3 blocks/SM): unchanged from R11 (~140us)
// ---------------------------------------------------------------------------
#define XCPA 136
#define WABP 72
__global__ __launch_bounds__(256, 3) void attn_kernel(
    const float* __restrict__ x, const float* __restrict__ A_base,
    const float* __restrict__ PA, const float* __restrict__ Wa,
    const float* __restrict__ ba, const float* __restrict__ Wb,
    const float* __restrict__ bb)
{
    extern __shared__ float sm[];
    float* sXc   = sm;                          // [64][136]
    float* sF    = sm + 64 * XCPA;              // [32][136]
    float* sWab  = sF + 32 * XCPA;              // [32][72]
    float* spart = sWab + 32 * WABP;            // [8][256]

    __shared__ float sbias[32];
    __shared__ float satt[256];
    __shared__ float colmax[16], colinv[16];

    const int tid  = threadIdx.x;
    const int wid  = tid >> 5;
    const int lane = tid & 31;
    const int n = blockIdx.x / S_;
    const int s = blockIdx.x % S_;

    const int r    = lane >> 2;
    const int kq   = lane & 3;
    const int ncol = lane >> 2;

    {
        int i = tid >> 3, c8 = (tid & 7) * 8;
        const float* src = (i < 16)
            ? (Wa + (size_t)(s * 16 + i) * 64 + c8)
            : (Wb + (size_t)(s * 16 + (i - 16)) * 64 + c8);
        *reinterpret_cast<float4*>(sWab + i * WABP + c8)     = *reinterpret_cast<const float4*>(src);
        *reinterpret_cast<float4*>(sWab + i * WABP + c8 + 4) = *reinterpret_cast<const float4*>(src + 4);
    }
    if (tid < 16)      sbias[tid] = ba[s * 16 + tid];
    else if (tid < 32) sbias[tid] = bb[s * 16 + (tid - 16)];

    const float* xn = x + (size_t)n * (C_ * T_ * V_);

    for (int idx = tid; idx < 2048; idx += 256) {
        int c = idx >> 5, q = idx & 31;
        *reinterpret_cast<float4*>(sXc + c * XCPA + q * 4) =
            *reinterpret_cast<const float4*>(xn + (size_t)c * (T_ * V_) + q * 4);
    }
    __syncthreads();

    const int mt = wid & 1;
    const int n0 = (wid >> 1) * 32;
    const float b_r  = sbias[mt * 16 + r];
    const float b_r8 = sbias[mt * 16 + r + 8];
    const int row0 = mt * 16 + r;

    float gacc[2][4];
    gacc[0][0] = 0.f; gacc[0][1] = 0.f; gacc[0][2] = 0.f; gacc[0][3] = 0.f;
    gacc[1][0] = 0.f; gacc[1][1] = 0.f; gacc[1][2] = 0.f; gacc[1][3] = 0.f;

    const uint32_t* uWab = reinterpret_cast<const uint32_t*>(sWab);
    const uint32_t* uXc  = reinterpret_cast<const uint32_t*>(sXc);
    const uint32_t* uF   = reinterpret_cast<const uint32_t*>(sF);

    const int i2 = 2 * wid;

    for (int ch = 0; ch < 36; ch++) {
        float acc[4][4];
        #pragma unroll
        for (int nt = 0; nt < 4; nt++) {
            acc[nt][0] = b_r; acc[nt][1] = b_r;
            acc[nt][2] = b_r8; acc[nt][3] = b_r8;
        }
        #pragma unroll
        for (int ks = 0; ks < 8; ks++) {
            const int k0 = ks * 8;
            uint32_t a0 = uWab[row0 * WABP + k0 + kq];
            uint32_t a1 = uWab[(row0 + 8) * WABP + k0 + kq];
            uint32_t a2 = uWab[row0 * WABP + k0 + 4 + kq];
            uint32_t a3 = uWab[(row0 + 8) * WABP + k0 + 4 + kq];
            const uint32_t* bp0 = uXc + (k0 + kq) * XCPA + n0 + ncol;
            const uint32_t* bp1 = uXc + (k0 + 4 + kq) * XCPA + n0 + ncol;
            #pragma unroll
            for (int nt = 0; nt < 4; nt++) {
                mma_tf32(acc[nt][0], acc[nt][1], acc[nt][2], acc[nt][3],
                         a0, a1, a2, a3, bp0[nt * 8], bp1[nt * 8]);
            }
        }
        #pragma unroll
        for (int nt = 0; nt < 4; nt++) {
            const int col = n0 + nt * 8 + 2 * kq;
            *reinterpret_cast<float2*>(sF + row0 * XCPA + col) =
                make_float2(acc[nt][0], acc[nt][1]);
            *reinterpret_cast<float2*>(sF + (row0 + 8) * XCPA + col) =
                make_float2(acc[nt][2], acc[nt][3]);
        }
        __syncthreads();

        if (ch < 35) {
            const float* src = xn + (ch + 1) * 128;
            for (int idx = tid; idx < 2048; idx += 256) {
                int c = idx >> 5, q = idx & 31;
                *reinterpret_cast<float4*>(sXc + c * XCPA + q * 4) =
                    *reinterpret_cast<const float4*>(src + (size_t)c * (T_ * V_) + q * 4);
            }
        }

        #pragma unroll
        for (int ks = 0; ks < 2; ks++) {
            const int i = i2 + ks;
            uint32_t a0 = uF[i * XCPA + kq * 16 + r];
            uint32_t a1 = uF[i * XCPA + kq * 16 + r + 8];
            uint32_t a2 = uF[i * XCPA + (kq + 4) * 16 + r];
            uint32_t a3 = uF[i * XCPA + (kq + 4) * 16 + r + 8];
            #pragma unroll
            for (int nt = 0; nt < 2; nt++) {
                uint32_t b0 = uF[(16 + i) * XCPA + kq * 16 + nt * 8 + ncol];
                uint32_t b1 = uF[(16 + i) * XCPA + (kq + 4) * 16 + nt * 8 + ncol];
                mma_tf32(gacc[nt][0], gacc[nt][1], gacc[nt][2], gacc[nt][3],
                         a0, a1, a2, a3, b0, b1);
            }
        }
        __syncthreads();
    }

    #pragma unroll
    for (int nt = 0; nt < 2; nt++) {
        float* p = spart + wid * 256 + nt * 8 + 2 * kq;
        p[r * 16]           = gacc[nt][0];
        p[r * 16 + 1]       = gacc[nt][1];
        p[(r + 8) * 16]     = gacc[nt][2];
        p[(r + 8) * 16 + 1] = gacc[nt][3];
    }
    __syncthreads();

    float attacc = 0.f;
    #pragma unroll
    for (int w8 = 0; w8 < 8; w8++) attacc += spart[w8 * 256 + tid];
    attacc *= (1.0f / (float)(IC_ * T_));
    satt[tid] = attacc;
    __syncthreads();

    const int v = tid >> 4;
    const int w = tid & 15;
    if (tid < 16) {
        float m = -1e30f;
        #pragma unroll
        for (int vv = 0; vv < 16; vv++) m = fmaxf(m, satt[vv * 16 + tid]);
        float ssum = 0.f;
        #pragma unroll
        for (int vv = 0; vv < 16; vv++) ssum += __expf(satt[vv * 16 + tid] - m);
        colmax[tid] = m;
        colinv[tid] = 1.0f / ssum;
    }
    __syncthreads();

    float rr = __expf(attacc - colmax[w]) * colinv[w]
             + A_base[(s * 16 + v) * 16 + w] + PA[(s * 16 + v) * 16 + w];
    g_att[((n * 3 + s) * 16 + v) * 16 + w] = rr;
}

// ---------------------------------------------------------------------------
// Kernel B v3: barrier-free s-loop.
//   All 3 Wd subsets staged once (u64 k-pair layout, R7-proven).
//   stage1 (mma): D = att_s^T @ X_t, warp-private fragments.
//   D -> stage2 A-fragments via __shfl_sync (bitwise same values as the old
//   smem round-trip). stage2 (mma): acc += Z @ W_s, B via LDS.128 of u64 pairs.
//   Block barriers: preamble, pre-epilogue, post-sO = 3 total.
// smem: sW3 50688 @0 (sO reuses) | sX 33792 @50688 | sAtt 3072 @84480 = 87552
// ---------------------------------------------------------------------------
#define XP 132
__global__ __launch_bounds__(256, 2) void out_kernel(
    const float* __restrict__ x, const float* __restrict__ Wd,
    const float* __restrict__ bd, const float* __restrict__ gamma,
    const float* __restrict__ beta, float* __restrict__ out)
{
    extern __shared__ char smem[];
    unsigned long long* sW3 = (unsigned long long*)(smem);   // 3 x [8kg][4kq][66]
    float* sO   = (float*)(smem);                            // epilogue reuse [64][XP]
    float* sX   = (float*)(smem + 50688);                    // [64][XP]
    float* sAtt = (float*)(smem + 84480);                    // [3][16][16]

    __shared__ float sBN[3 * 64];

    const int tid  = threadIdx.x;
    const int wid  = tid >> 5;
    const int lane = tid & 31;
    const int n  = blockIdx.y;
    const int t0 = blockIdx.x * 8;

    // ---- preamble
    for (int idx = tid; idx < 768; idx += 256)
        sAtt[idx] = g_att[n * 768 + idx];
    for (int idx = tid; idx < 64 * 32; idx += 256) {
        int c = idx >> 5, q = idx & 31;
        reinterpret_cast<float4*>(sX + c * XP)[q] =
            reinterpret_cast<const float4*>(x + (size_t)(n * 64 + c) * (T_ * V_) + t0 * V_)[q];
    }
    // W staging: all 3 s, u64 (b0,b1) k-pair layout, o permuted
    {
        const int wo  = tid & 63;
        const int wkb = tid >> 6;
        const int wop = (wo & 7) * 8 + (wo >> 3);
        #pragma unroll
        for (int s = 0; s < S_; s++) {
            const float4* src = reinterpret_cast<const float4*>(
                Wd + (size_t)s * 4096 + (size_t)wo * 64 + wkb * 16);
            float4 wv[4];
            #pragma unroll
            for (int q = 0; q < 4; q++) wv[q] = src[q];
            const float* wf = (const float*)wv;
            #pragma unroll
            for (int kgl = 0; kgl < 2; kgl++) {
                int kg = 2 * wkb + kgl;
                #pragma unroll
                for (int kql = 0; kql < 4; kql++) {
                    uint32_t lo = f2tf32(wf[kgl * 8 + kql]);
                    uint32_t hi = f2tf32(wf[kgl * 8 + kql + 4]);
                    sW3[s * 2112 + (kg * 4 + kql) * 66 + wop] =
                        ((unsigned long long)hi << 32) | lo;
                }
            }
        }
    }
    if (tid < 64) {
        int o = tid;
        sBN[o]       = bd[o] + bd[64 + o] + bd[128 + o];
        sBN[64 + o]  = gamma[o] * rsqrtf(1.0f + 1e-5f);
        sBN[128 + o] = beta[o];
    }
    __syncthreads();

    const int r    = lane >> 2;
    const int kq   = lane & 3;
    const int ncol = lane >> 2;

    const uint32_t* uX = reinterpret_cast<const uint32_t*>(sX);
    const uint32_t* uA = reinterpret_cast<const uint32_t*>(sAtt);

    const int srcA = (lane & 28) | (kq >> 1);
    const int srcB = srcA + 2;
    const bool odd = (kq & 1) != 0;

    float acc[8][4];
    #pragma unroll
    for (int nf = 0; nf < 8; nf++) {
        acc[nf][0] = 0.f; acc[nf][1] = 0.f; acc[nf][2] = 0.f; acc[nf][3] = 0.f;
    }

    #pragma unroll
    for (int s = 0; s < S_; s++) {
        // ---- stage1 (tensor): D = att_s^T @ X_t  (warp-private)
        float d[8][4];
        #pragma unroll
        for (int nf = 0; nf < 8; nf++) {
            d[nf][0] = 0.f; d[nf][1] = 0.f; d[nf][2] = 0.f; d[nf][3] = 0.f;
        }
        #pragma unroll
        for (int ks = 0; ks < 2; ks++) {
            const int v0 = ks * 8 + kq;
            uint32_t a0 = uA[s * 256 + v0 * 16 + r];
            uint32_t a1 = uA[s * 256 + v0 * 16 + r + 8];
            uint32_t a2 = uA[s * 256 + (v0 + 4) * 16 + r];
            uint32_t a3 = uA[s * 256 + (v0 + 4) * 16 + r + 8];
            const uint32_t* bx = uX + wid * 16 + ks * 8 + kq;
            #pragma unroll
            for (int nf = 0; nf < 8; nf++) {
                uint32_t b0 = bx[(nf * 8 + ncol) * XP];
                uint32_t b1 = bx[(nf * 8 + ncol) * XP + 4];
                mma_tf32(d[nf][0], d[nf][1], d[nf][2], d[nf][3],
                         a0, a1, a2, a3, b0, b1);
            }
        }

        // ---- stage2: per k-step, A-frags via shfl from d, B from sW3
        const unsigned long long* sWs = sW3 + s * 2112;
        #pragma unroll
        for (int ks = 0; ks < 8; ks++) {
            float e0 = __shfl_sync(0xffffffffu, d[ks][0], srcA);
            float e1 = __shfl_sync(0xffffffffu, d[ks][1], srcA);
            float e2 = __shfl_sync(0xffffffffu, d[ks][2], srcA);
            float e3 = __shfl_sync(0xffffffffu, d[ks][3], srcA);
            float g0 = __shfl_sync(0xffffffffu, d[ks][0], srcB);
            float g1 = __shfl_sync(0xffffffffu, d[ks][1], srcB);
            float g2 = __shfl_sync(0xffffffffu, d[ks][2], srcB);
            float g3 = __shfl_sync(0xffffffffu, d[ks][3], srcB);
            uint32_t a0 = f2tf32(odd ? e1 : e0);
            uint32_t a1 = f2tf32(odd ? e3 : e2);
            uint32_t a2 = f2tf32(odd ? g1 : g0);
            uint32_t a3 = f2tf32(odd ? g3 : g2);

            const unsigned long long* brow = sWs + (ks * 4 + kq) * 66 + ncol * 8;
            #pragma unroll
            for (int p = 0; p < 4; p++) {
                uint4 bb = *reinterpret_cast<const uint4*>(brow + 2 * p);
                mma_tf32(acc[2 * p][0], acc[2 * p][1], acc[2 * p][2], acc[2 * p][3],
                         a0, a1, a2, a3, bb.x, bb.y);
                mma_tf32(acc[2 * p + 1][0], acc[2 * p + 1][1],
                         acc[2 * p + 1][2], acc[2 * p + 1][3],
                         a0, a1, a2, a3, bb.z, bb.w);
            }
        }
    }

    __syncthreads();   // all warps done reading sW3 (and sX stage1 reads)

    // ---- epilogue: BN+bias into sO[o][tw] (pitch 132), coalesced store
    {
        const int r0 = wid * 16 + r;
        #pragma unroll
        for (int nf = 0; nf < 8; nf++) {
            int o0 = nf * 8 + 2 * kq;
            float s0 = sBN[64 + o0],     b0v = sBN[o0],     z0 = sBN[128 + o0];
            float s1 = sBN[64 + o0 + 1], b1v = sBN[o0 + 1], z1 = sBN[128 + o0 + 1];
            sO[o0 * XP + r0]           = (acc[nf][0] + b0v) * s0 + z0;
            sO[(o0 + 1) * XP + r0]     = (acc[nf][1] + b1v) * s1 + z1;
            sO[o0 * XP + r0 + 8]       = (acc[nf][2] + b0v) * s0 + z0;
            sO[(o0 + 1) * XP + r0 + 8] = (acc[nf][3] + b1v) * s1 + z1;
        }
    }
    __syncthreads();

    for (int idx = tid; idx < 64 * 32; idx += 256) {
        int c = idx >> 5, q = idx & 31;
        float4 yv = reinterpret_cast<const float4*>(sO + c * XP)[q];
        float4 xv = reinterpret_cast<const float4*>(sX + c * XP)[q];
        yv.x += xv.x; yv.y += xv.y; yv.z += xv.z; yv.w += xv.w;
        reinterpret_cast<float4*>(out + (size_t)(n * 64 + c) * (T_ * V_) + t0 * V_)[q] = yv;
    }
}

extern "C" void kernel_launch(void* const* d_in, const int* in_sizes, int n_in,
                              void* d_out, int out_size)
{
    const float* x      = (const float*)d_in[0];
    const float* A_base = (const float*)d_in[1];
    const float* PA     = (const float*)d_in[2];
    const float* Wa     = (const float*)d_in[3];
    const float* ba     = (const float*)d_in[4];
    const float* Wb     = (const float*)d_in[5];
    const float* bb     = (const float*)d_in[6];
    const float* Wd     = (const float*)d_in[7];
    const float* bd     = (const float*)d_in[8];
    const float* gamma  = (const float*)d_in[9];
    const float* beta   = (const float*)d_in[10];
    float* out = (float*)d_out;

    const int smemA = (64 * XCPA + 32 * XCPA + 32 * WABP + 8 * 256) * sizeof(float); // 69632 B
    const int smemB = 87552;                                                         // bytes

    cudaFuncSetAttribute(attn_kernel, cudaFuncAttributeMaxDynamicSharedMemorySize, smemA);
    cudaFuncSetAttribute(out_kernel,  cudaFuncAttributeMaxDynamicSharedMemorySize, smemB);

    attn_kernel<<<N_ * S_, 256, smemA>>>(x, A_base, PA, Wa, ba, Wb, bb);
    out_kernel<<<dim3(T_ / 8, N_), 256, smemB>>>(x, Wd, bd, gamma, beta, out);
}

// round 15
// speedup vs baseline: 1.1479x; 1.0518x over previous
#include <cuda_runtime.h>
#include <cstdint>

#define N_  128
#define C_  64
#define T_  288
#define V_  16
#define S_  3
#define IC_ 16

// tiny scratch: attention matrices after softmax + A  [N, S, V, V]
__device__ float g_att[N_ * S_ * V_ * V_];

// ---- helpers ------------------------------------------------------------
__device__ __forceinline__ uint32_t f2tf32(float f) {
    uint32_t r;
    asm("cvt.rna.tf32.f32 %0, %1;" : "=r"(r) : "f"(f));
    return r;
}
__device__ __forceinline__ void mma_tf32(float& d0, float& d1, float& d2, float& d3,
                                         uint32_t a0, uint32_t a1, uint32_t a2, uint32_t a3,
                                         uint32_t b0, uint32_t b1) {
    asm volatile("mma.sync.aligned.m16n8k8.row.col.f32.tf32.tf32.f32 "
                 "{%0,%1,%2,%3}, {%4,%5,%6,%7}, {%8,%9}, {%0,%1,%2,%3};"
                 : "+f"(d0), "+f"(d1), "+f"(d2), "+f"(d3)
                 : "r"(a0), "r"(a1), "r"(a2), "r"(a3), "r"(b0), "r"(b1));
}

// ---------------------------------------------------------------------------
// Kernel A (tensor, 8-t chunks, 3 blocks/SM): unchanged from R11 (~140us)
// ---------------------------------------------------------------------------
#define XCPA 136
#define WABP 72
__global__ __launch_bounds__(256, 3) void attn_kernel(
    const float* __restrict__ x, const float* __restrict__ A_base,
    const float* __restrict__ PA, const float* __restrict__ Wa,
    const float* __restrict__ ba, const float* __restrict__ Wb,
    const float* __restrict__ bb)
{
    extern __shared__ float sm[];
    float* sXc   = sm;                          // [64][136]
    float* sF    = sm + 64 * XCPA;              // [32][136]
    float* sWab  = sF + 32 * XCPA;              // [32][72]
    float* spart = sWab + 32 * WABP;            // [8][256]

    __shared__ float sbias[32];
    __shared__ float satt[256];
    __shared__ float colmax[16], colinv[16];

    const int tid  = threadIdx.x;
    const int wid  = tid >> 5;
    const int lane = tid & 31;
    const int n = blockIdx.x / S_;
    const int s = blockIdx.x % S_;

    const int r    = lane >> 2;
    const int kq   = lane & 3;
    const int ncol = lane >> 2;

    {
        int i = tid >> 3, c8 = (tid & 7) * 8;
        const float* src = (i < 16)
            ? (Wa + (size_t)(s * 16 + i) * 64 + c8)
            : (Wb + (size_t)(s * 16 + (i - 16)) * 64 + c8);
        *reinterpret_cast<float4*>(sWab + i * WABP + c8)     = *reinterpret_cast<const float4*>(src);
        *reinterpret_cast<float4*>(sWab + i * WABP + c8 + 4) = *reinterpret_cast<const float4*>(src + 4);
    }
    if (tid < 16)      sbias[tid] = ba[s * 16 + tid];
    else if (tid < 32) sbias[tid] = bb[s * 16 + (tid - 16)];

    const float* xn = x + (size_t)n * (C_ * T_ * V_);

    for (int idx = tid; idx < 2048; idx += 256) {
        int c = idx >> 5, q = idx & 31;
        *reinterpret_cast<float4*>(sXc + c * XCPA + q * 4) =
            *reinterpret_cast<const float4*>(xn + (size_t)c * (T_ * V_) + q * 4);
    }
    __syncthreads();

    const int mt = wid & 1;
    const int n0 = (wid >> 1) * 32;
    const float b_r  = sbias[mt * 16 + r];
    const float b_r8 = sbias[mt * 16 + r + 8];
    const int row0 = mt * 16 + r;

    float gacc[2][4];
    gacc[0][0] = 0.f; gacc[0][1] = 0.f; gacc[0][2] = 0.f; gacc[0][3] = 0.f;
    gacc[1][0] = 0.f; gacc[1][1] = 0.f; gacc[1][2] = 0.f; gacc[1][3] = 0.f;

    const uint32_t* uWab = reinterpret_cast<const uint32_t*>(sWab);
    const uint32_t* uXc  = reinterpret_cast<const uint32_t*>(sXc);
    const uint32_t* uF   = reinterpret_cast<const uint32_t*>(sF);

    const int i2 = 2 * wid;

    for (int ch = 0; ch < 36; ch++) {
        float acc[4][4];
        #pragma unroll
        for (int nt = 0; nt < 4; nt++) {
            acc[nt][0] = b_r; acc[nt][1] = b_r;
            acc[nt][2] = b_r8; acc[nt][3] = b_r8;
        }
        #pragma unroll
        for (int ks = 0; ks < 8; ks++) {
            const int k0 = ks * 8;
            uint32_t a0 = uWab[row0 * WABP + k0 + kq];
            uint32_t a1 = uWab[(row0 + 8) * WABP + k0 + kq];
            uint32_t a2 = uWab[row0 * WABP + k0 + 4 + kq];
            uint32_t a3 = uWab[(row0 + 8) * WABP + k0 + 4 + kq];
            const uint32_t* bp0 = uXc + (k0 + kq) * XCPA + n0 + ncol;
            const uint32_t* bp1 = uXc + (k0 + 4 + kq) * XCPA + n0 + ncol;
            #pragma unroll
            for (int nt = 0; nt < 4; nt++) {
                mma_tf32(acc[nt][0], acc[nt][1], acc[nt][2], acc[nt][3],
                         a0, a1, a2, a3, bp0[nt * 8], bp1[nt * 8]);
            }
        }
        #pragma unroll
        for (int nt = 0; nt < 4; nt++) {
            const int col = n0 + nt * 8 + 2 * kq;
            *reinterpret_cast<float2*>(sF + row0 * XCPA + col) =
                make_float2(acc[nt][0], acc[nt][1]);
            *reinterpret_cast<float2*>(sF + (row0 + 8) * XCPA + col) =
                make_float2(acc[nt][2], acc[nt][3]);
        }
        __syncthreads();

        if (ch < 35) {
            const float* src = xn + (ch + 1) * 128;
            for (int idx = tid; idx < 2048; idx += 256) {
                int c = idx >> 5, q = idx & 31;
                *reinterpret_cast<float4*>(sXc + c * XCPA + q * 4) =
                    *reinterpret_cast<const float4*>(src + (size_t)c * (T_ * V_) + q * 4);
            }
        }

        #pragma unroll
        for (int ks = 0; ks < 2; ks++) {
            const int i = i2 + ks;
            uint32_t a0 = uF[i * XCPA + kq * 16 + r];
            uint32_t a1 = uF[i * XCPA + kq * 16 + r + 8];
            uint32_t a2 = uF[i * XCPA + (kq + 4) * 16 + r];
            uint32_t a3 = uF[i * XCPA + (kq + 4) * 16 + r + 8];
            #pragma unroll
            for (int nt = 0; nt < 2; nt++) {
                uint32_t b0 = uF[(16 + i) * XCPA + kq * 16 + nt * 8 + ncol];
                uint32_t b1 = uF[(16 + i) * XCPA + (kq + 4) * 16 + nt * 8 + ncol];
                mma_tf32(gacc[nt][0], gacc[nt][1], gacc[nt][2], gacc[nt][3],
                         a0, a1, a2, a3, b0, b1);
            }
        }
        __syncthreads();
    }

    #pragma unroll
    for (int nt = 0; nt < 2; nt++) {
        float* p = spart + wid * 256 + nt * 8 + 2 * kq;
        p[r * 16]           = gacc[nt][0];
        p[r * 16 + 1]       = gacc[nt][1];
        p[(r + 8) * 16]     = gacc[nt][2];
        p[(r + 8) * 16 + 1] = gacc[nt][3];
    }
    __syncthreads();

    float attacc = 0.f;
    #pragma unroll
    for (int w8 = 0; w8 < 8; w8++) attacc += spart[w8 * 256 + tid];
    attacc *= (1.0f / (float)(IC_ * T_));
    satt[tid] = attacc;
    __syncthreads();

    const int v = tid >> 4;
    const int w = tid & 15;
    if (tid < 16) {
        float m = -1e30f;
        #pragma unroll
        for (int vv = 0; vv < 16; vv++) m = fmaxf(m, satt[vv * 16 + tid]);
        float ssum = 0.f;
        #pragma unroll
        for (int vv = 0; vv < 16; vv++) ssum += __expf(satt[vv * 16 + tid] - m);
        colmax[tid] = m;
        colinv[tid] = 1.0f / ssum;
    }
    __syncthreads();

    float rr = __expf(attacc - colmax[w]) * colinv[w]
             + A_base[(s * 16 + v) * 16 + w] + PA[(s * 16 + v) * 16 + w];
    g_att[((n * 3 + s) * 16 + v) * 16 + w] = rr;
}

// ---------------------------------------------------------------------------
// Kernel B v4: shuffle-free stage1->stage2 handoff.
//   Contraction slots relabeled: k-slot kq carries channel c=8ks+2kq, slot
//   kq+4 carries c=8ks+2kq+1. With that, each thread's stage1 D-fragment IS
//   its stage2 A-fragment (a0=d0, a1=d2, a2=d1, a3=d3) — no shfl, no sel.
//   W staged with consecutive-c u64 pairs to match: u64(kg,kql) =
//   (W[c=8kg+2kql], W[c=8kg+2kql+1]).
// smem: sW3 50688 @0 (sO reuses) | sX 33792 @50688 | sAtt 3072 @84480 = 87552
// ---------------------------------------------------------------------------
#define XP 132
__global__ __launch_bounds__(256, 2) void out_kernel(
    const float* __restrict__ x, const float* __restrict__ Wd,
    const float* __restrict__ bd, const float* __restrict__ gamma,
    const float* __restrict__ beta, float* __restrict__ out)
{
    extern __shared__ char smem[];
    unsigned long long* sW3 = (unsigned long long*)(smem);   // 3 x [8kg][4kq][66]
    float* sO   = (float*)(smem);                            // epilogue reuse [64][XP]
    float* sX   = (float*)(smem + 50688);                    // [64][XP]
    float* sAtt = (float*)(smem + 84480);                    // [3][16][16]

    __shared__ float sBN[3 * 64];

    const int tid  = threadIdx.x;
    const int wid  = tid >> 5;
    const int lane = tid & 31;
    const int n  = blockIdx.y;
    const int t0 = blockIdx.x * 8;

    // ---- preamble
    for (int idx = tid; idx < 768; idx += 256)
        sAtt[idx] = g_att[n * 768 + idx];
    for (int idx = tid; idx < 64 * 32; idx += 256) {
        int c = idx >> 5, q = idx & 31;
        reinterpret_cast<float4*>(sX + c * XP)[q] =
            reinterpret_cast<const float4*>(x + (size_t)(n * 64 + c) * (T_ * V_) + t0 * V_)[q];
    }
    // W staging: all 3 s; u64(kg,kql) = (W[c=8kg+2kql], W[c=8kg+2kql+1])
    {
        const int wo  = tid & 63;
        const int wkb = tid >> 6;
        const int wop = (wo & 7) * 8 + (wo >> 3);
        #pragma unroll
        for (int s = 0; s < S_; s++) {
            const float4* src = reinterpret_cast<const float4*>(
                Wd + (size_t)s * 4096 + (size_t)wo * 64 + wkb * 16);
            float4 wv[4];
            #pragma unroll
            for (int q = 0; q < 4; q++) wv[q] = src[q];
            const float* wf = (const float*)wv;   // c-local 0..15 (c = wkb*16 + i)
            #pragma unroll
            for (int pp = 0; pp < 8; pp++) {
                int kg  = 2 * wkb + (pp >> 2);
                int kql = pp & 3;
                uint32_t lo = f2tf32(wf[2 * pp]);
                uint32_t hi = f2tf32(wf[2 * pp + 1]);
                sW3[s * 2112 + (kg * 4 + kql) * 66 + wop] =
                    ((unsigned long long)hi << 32) | lo;
            }
        }
    }
    if (tid < 64) {
        int o = tid;
        sBN[o]       = bd[o] + bd[64 + o] + bd[128 + o];
        sBN[64 + o]  = gamma[o] * rsqrtf(1.0f + 1e-5f);
        sBN[128 + o] = beta[o];
    }
    __syncthreads();

    const int r    = lane >> 2;
    const int kq   = lane & 3;
    const int ncol = lane >> 2;

    const uint32_t* uX = reinterpret_cast<const uint32_t*>(sX);
    const uint32_t* uA = reinterpret_cast<const uint32_t*>(sAtt);

    float acc[8][4];
    #pragma unroll
    for (int nf = 0; nf < 8; nf++) {
        acc[nf][0] = 0.f; acc[nf][1] = 0.f; acc[nf][2] = 0.f; acc[nf][3] = 0.f;
    }

    #pragma unroll
    for (int s = 0; s < S_; s++) {
        // ---- stage1 (tensor): D = att_s^T @ X_t  (warp-private)
        // D n-tile nf covers channels c = nf*8 .. +7; this thread's D cols
        // within the tile are 2kq, 2kq+1.
        float d[8][4];
        #pragma unroll
        for (int nf = 0; nf < 8; nf++) {
            d[nf][0] = 0.f; d[nf][1] = 0.f; d[nf][2] = 0.f; d[nf][3] = 0.f;
        }
        #pragma unroll
        for (int ks = 0; ks < 2; ks++) {
            const int v0 = ks * 8 + kq;
            uint32_t a0 = uA[s * 256 + v0 * 16 + r];
            uint32_t a1 = uA[s * 256 + v0 * 16 + r + 8];
            uint32_t a2 = uA[s * 256 + (v0 + 4) * 16 + r];
            uint32_t a3 = uA[s * 256 + (v0 + 4) * 16 + r + 8];
            const uint32_t* bx = uX + wid * 16 + ks * 8 + kq;
            #pragma unroll
            for (int nf = 0; nf < 8; nf++) {
                uint32_t b0 = bx[(nf * 8 + ncol) * XP];
                uint32_t b1 = bx[(nf * 8 + ncol) * XP + 4];
                mma_tf32(d[nf][0], d[nf][1], d[nf][2], d[nf][3],
                         a0, a1, a2, a3, b0, b1);
            }
        }

        // ---- stage2: A-frags ARE the D-frags (slot relabeling); B from sW3
        const unsigned long long* sWs = sW3 + s * 2112;
        #pragma unroll
        for (int ks = 0; ks < 8; ks++) {
            uint32_t a0 = f2tf32(d[ks][0]);   // (r,   c=8ks+2kq)   -> k-slot kq
            uint32_t a1 = f2tf32(d[ks][2]);   // (r+8, c=8ks+2kq)
            uint32_t a2 = f2tf32(d[ks][1]);   // (r,   c=8ks+2kq+1) -> k-slot kq+4
            uint32_t a3 = f2tf32(d[ks][3]);   // (r+8, c=8ks+2kq+1)

            const unsigned long long* brow = sWs + (ks * 4 + kq) * 66 + ncol * 8;
            #pragma unroll
            for (int p = 0; p < 4; p++) {
                uint4 bb = *reinterpret_cast<const uint4*>(brow + 2 * p);
                mma_tf32(acc[2 * p][0], acc[2 * p][1], acc[2 * p][2], acc[2 * p][3],
                         a0, a1, a2, a3, bb.x, bb.y);
                mma_tf32(acc[2 * p + 1][0], acc[2 * p + 1][1],
                         acc[2 * p + 1][2], acc[2 * p + 1][3],
                         a0, a1, a2, a3, bb.z, bb.w);
            }
        }
    }

    __syncthreads();   // all warps done reading sW3 / sX stage1 reads

    // ---- epilogue: BN+bias into sO[o][tw] (pitch 132), coalesced store
    {
        const int r0 = wid * 16 + r;
        #pragma unroll
        for (int nf = 0; nf < 8; nf++) {
            int o0 = nf * 8 + 2 * kq;
            float s0 = sBN[64 + o0],     b0v = sBN[o0],     z0 = sBN[128 + o0];
            float s1 = sBN[64 + o0 + 1], b1v = sBN[o0 + 1], z1 = sBN[128 + o0 + 1];
            sO[o0 * XP + r0]           = (acc[nf][0] + b0v) * s0 + z0;
            sO[(o0 + 1) * XP + r0]     = (acc[nf][1] + b1v) * s1 + z1;
            sO[o0 * XP + r0 + 8]       = (acc[nf][2] + b0v) * s0 + z0;
            sO[(o0 + 1) * XP + r0 + 8] = (acc[nf][3] + b1v) * s1 + z1;
        }
    }
    __syncthreads();

    for (int idx = tid; idx < 64 * 32; idx += 256) {
        int c = idx >> 5, q = idx & 31;
        float4 yv = reinterpret_cast<const float4*>(sO + c * XP)[q];
        float4 xv = reinterpret_cast<const float4*>(sX + c * XP)[q];
        yv.x += xv.x; yv.y += xv.y; yv.z += xv.z; yv.w += xv.w;
        reinterpret_cast<float4*>(out + (size_t)(n * 64 + c) * (T_ * V_) + t0 * V_)[q] = yv;
    }
}

extern "C" void kernel_launch(void* const* d_in, const int* in_sizes, int n_in,
                              void* d_out, int out_size)
{
    const float* x      = (const float*)d_in[0];
    const float* A_base = (const float*)d_in[1];
    const float* PA     = (const float*)d_in[2];
    const float* Wa     = (const float*)d_in[3];
    const float* ba     = (const float*)d_in[4];
    const float* Wb     = (const float*)d_in[5];
    const float* bb     = (const float*)d_in[6];
    const float* Wd     = (const float*)d_in[7];
    const float* bd     = (const float*)d_in[8];
    const float* gamma  = (const float*)d_in[9];
    const float* beta   = (const float*)d_in[10];
    float* out = (float*)d_out;

    const int smemA = (64 * XCPA + 32 * XCPA + 32 * WABP + 8 * 256) * sizeof(float); // 69632 B
    const int smemB = 87552;                                                         // bytes

    cudaFuncSetAttribute(attn_kernel, cudaFuncAttributeMaxDynamicSharedMemorySize, smemA);
    cudaFuncSetAttribute(out_kernel,  cudaFuncAttributeMaxDynamicSharedMemorySize, smemB);

    attn_kernel<<<N_ * S_, 256, smemA>>>(x, A_base, PA, Wa, ba, Wb, bb);
    out_kernel<<<dim3(T_ / 8, N_), 256, smemB>>>(x, Wd, bd, gamma, beta, out);
}